// round 17
// baseline (speedup 1.0000x reference)
#include <cuda_runtime.h>
#include <cuda_fp16.h>
#include <math.h>
#include <stdint.h>

// ---------------- constants ----------------
#define BATCH   2
#define SEQ     4096
#define ROWS    (BATCH*SEQ)        // 8192
#define DMODEL  2048
#define DSTATE  64
#define DHEAD   64
#define NHEADS  32
#define CHUNK   64
#define NCHUNK  (SEQ/CHUNK)        // 64
#define CONVD   6144
#define ZXB_LD  8192               // output cols of GEMM1 (dt cols unused)
#define RMS_EPS 1.1920929e-07f

// ---------------- scratch ----------------
__device__ float  g_z   [(size_t)ROWS * DMODEL];   // z (gate input), fp32
__device__ __half g_xbch[(size_t)ROWS * CONVD];    // xBC pre-conv, fp16
__device__ __half g_ch  [(size_t)ROWS * DMODEL];   // silu(conv(C)) compact, fp16
__device__ __half g_y   [(size_t)ROWS * DMODEL];   // Y_diag, fp16
__device__ __half g_yn  [(size_t)ROWS * DMODEL];   // gated+rmsnormed, fp16
__device__ float  g_cs  [(size_t)BATCH*NHEADS*NCHUNK*DSTATE];
__device__ float  g_prev[(size_t)BATCH*NHEADS*NCHUNK*DSTATE];
__device__ __half g_ut  [(size_t)ROWS * DMODEL];
__device__ __half g_wit [(size_t)ZXB_LD * DMODEL];
__device__ __half g_wot [(size_t)DMODEL * DMODEL];

// ---------------- helpers ----------------
__device__ __forceinline__ void cp16(void* dst, const void* src) {
    unsigned saddr = (unsigned)__cvta_generic_to_shared(dst);
    asm volatile("cp.async.cg.shared.global [%0], [%1], 16;" :: "r"(saddr), "l"(src));
}
__device__ __forceinline__ void sts_zero16(void* dst) {
    unsigned saddr = (unsigned)__cvta_generic_to_shared(dst);
    asm volatile("st.shared.v4.u32 [%0], {%1,%1,%1,%1};" :: "r"(saddr), "r"(0u));
}
__device__ __forceinline__ float silu(float v) {
    return __fdividef(v, 1.f + __expf(-v));
}

// one launch converting u, W_in, W_out to fp16
__global__ void h_convert3(const float* __restrict__ a, __half* __restrict__ oa, size_t na4,
                           const float* __restrict__ b, __half* __restrict__ ob, size_t nb4,
                           const float* __restrict__ c, __half* __restrict__ oc, size_t nc4)
{
    size_t i = (size_t)blockIdx.x * blockDim.x + threadIdx.x;
    const float* in;
    __half* out;
    if (i < na4) { in = a; out = oa; }
    else if (i < na4 + nb4) { i -= na4; in = b; out = ob; }
    else if (i < na4 + nb4 + nc4) { i -= na4 + nb4; in = c; out = oc; }
    else return;
    float4 v = ((const float4*)in)[i];
    __half2 lo = __floats2half2_rn(v.x, v.y);
    __half2 hi = __floats2half2_rn(v.z, v.w);
    uint2 o;
    o.x = *(unsigned*)&lo;
    o.y = *(unsigned*)&hi;
    ((uint2*)out)[i] = o;
}

// ============================================================================
// GEMM: C[M,N] = A[M,K] * B[N,K]^T ; fp16 in, fp32 acc.
// Block 128x128, warp tile 64x32, K-tile 64, SW128 swizzle, m16n8k16,
// 3-stage cp.async ring, one sync per K-tile, 2 CTAs/SM.
// B fragments: 2x ldmatrix.x4 per k-step (paired-nt lane mapping, verified
// in the R9 128x256 kernel) instead of 4x ldmatrix.x2.
// ============================================================================
#define NSTG  3
#define KT    64
#define ASZ   (128 * 32)
#define STG   (2 * ASZ)
#define GSMEM (NSTG * STG * 4)      // 98304 B

template<bool SPLIT>
__global__ __launch_bounds__(256, 2) void gemm_tn_f16(
    const __half* __restrict__ A, const __half* __restrict__ B,
    float* __restrict__ Cz, __half* __restrict__ Ch, int M, int N, int K)
{
    extern __shared__ __align__(16) unsigned sm[];

    const int tid  = threadIdx.x;
    const int row0 = blockIdx.y * 128;
    const int col0 = blockIdx.x * 128;
    const int warp = tid >> 5, lane = tid & 31;
    const int wm = warp >> 2, wn = warp & 3;

    float acc[4][4][4];
#pragma unroll
    for (int i = 0; i < 4; i++)
#pragma unroll
        for (int j = 0; j < 4; j++)
#pragma unroll
            for (int k = 0; k < 4; k++) acc[i][j][k] = 0.f;

    const __half* Ag = A + (size_t)row0 * K;
    const __half* Bg = B + (size_t)col0 * K;
    const int NT = K / KT;

    auto issue = [&](int j) {
        unsigned* as = sm + (j % NSTG) * STG;
        unsigned* bs = as + ASZ;
        int k0 = j * KT;
#pragma unroll
        for (int i = 0; i < 4; i++) {
            int ch = tid + i * 256;
            int r = ch >> 3, c = ch & 7;
            cp16(&as[r * 32 + ((c ^ (r & 7)) << 2)], Ag + (size_t)r * K + k0 + c * 8);
        }
#pragma unroll
        for (int i = 0; i < 4; i++) {
            int ch = tid + i * 256;
            int r = ch >> 3, c = ch & 7;
            cp16(&bs[r * 32 + ((c ^ (r & 7)) << 2)], Bg + (size_t)r * K + k0 + c * 8);
        }
        asm volatile("cp.async.commit_group;");
    };

    issue(0);
    if (NT > 1) issue(1);

    const unsigned smb = (unsigned)__cvta_generic_to_shared(sm);
    const int arow = wm * 64 + (lane & 15);
    const int acs  = lane >> 4;
    const int brow = wn * 32 + ((lane >> 4) << 3) + (lane & 7);  // + p*16
    const int bcs  = (lane >> 3) & 1;

    for (int t = 0; t < NT; t++) {
        if (t + 1 < NT) {
            asm volatile("cp.async.wait_group 1;");
        } else {
            asm volatile("cp.async.wait_group 0;");
        }
        __syncthreads();
        if (t + 2 < NT) issue(t + 2);

        const unsigned sb = smb + (unsigned)(t % NSTG) * (STG * 4);

#pragma unroll
        for (int ks = 0; ks < 4; ks++) {
            unsigned a[4][4], bf[4][2];
#pragma unroll
            for (int mt = 0; mt < 4; mt++) {
                int r = arow + mt * 16;
                unsigned ad = sb + (unsigned)(r * 128 + (((2 * ks + acs) ^ (r & 7)) << 4));
                asm volatile(
                    "ldmatrix.sync.aligned.m8n8.x4.shared.b16 {%0,%1,%2,%3}, [%4];"
                    : "=r"(a[mt][0]), "=r"(a[mt][1]), "=r"(a[mt][2]), "=r"(a[mt][3])
                    : "r"(ad));
            }
#pragma unroll
            for (int p = 0; p < 2; p++) {
                int r = brow + p * 16;
                unsigned bd = sb + (unsigned)(ASZ * 4) +
                              (unsigned)(r * 128 + (((2 * ks + bcs) ^ (r & 7)) << 4));
                asm volatile(
                    "ldmatrix.sync.aligned.m8n8.x4.shared.b16 {%0,%1,%2,%3}, [%4];"
                    : "=r"(bf[2 * p][0]), "=r"(bf[2 * p][1]),
                      "=r"(bf[2 * p + 1][0]), "=r"(bf[2 * p + 1][1])
                    : "r"(bd));
            }
#pragma unroll
            for (int mt = 0; mt < 4; mt++)
#pragma unroll
                for (int nt = 0; nt < 4; nt++)
                    asm volatile(
                        "mma.sync.aligned.m16n8k16.row.col.f32.f16.f16.f32 "
                        "{%0,%1,%2,%3}, {%4,%5,%6,%7}, {%8,%9}, {%0,%1,%2,%3};"
                        : "+f"(acc[mt][nt][0]), "+f"(acc[mt][nt][1]),
                          "+f"(acc[mt][nt][2]), "+f"(acc[mt][nt][3])
                        : "r"(a[mt][0]), "r"(a[mt][1]), "r"(a[mt][2]), "r"(a[mt][3]),
                          "r"(bf[nt][0]), "r"(bf[nt][1]));
        }
    }

    const int gg = lane >> 2, tt = lane & 3;
    if (!SPLIT) {
#pragma unroll
        for (int mt = 0; mt < 4; mt++) {
            int r = row0 + wm * 64 + mt * 16 + gg;
#pragma unroll
            for (int nt = 0; nt < 4; nt++) {
                int cc = col0 + wn * 32 + nt * 8 + 2 * tt;
                *(float2*)&Cz[(size_t)r * N + cc]       = make_float2(acc[mt][nt][0], acc[mt][nt][1]);
                *(float2*)&Cz[(size_t)(r + 8) * N + cc] = make_float2(acc[mt][nt][2], acc[mt][nt][3]);
            }
        }
    } else if (col0 < DMODEL) {
#pragma unroll
        for (int mt = 0; mt < 4; mt++) {
            int r = row0 + wm * 64 + mt * 16 + gg;
#pragma unroll
            for (int nt = 0; nt < 4; nt++) {
                int cc = col0 + wn * 32 + nt * 8 + 2 * tt;
                *(float2*)&Cz[(size_t)r * DMODEL + cc]       = make_float2(acc[mt][nt][0], acc[mt][nt][1]);
                *(float2*)&Cz[(size_t)(r + 8) * DMODEL + cc] = make_float2(acc[mt][nt][2], acc[mt][nt][3]);
            }
        }
    } else {
#pragma unroll
        for (int mt = 0; mt < 4; mt++) {
            int r = row0 + wm * 64 + mt * 16 + gg;
#pragma unroll
            for (int nt = 0; nt < 4; nt++) {
                int cc = col0 - DMODEL + wn * 32 + nt * 8 + 2 * tt;
                __half2 h0 = __floats2half2_rn(acc[mt][nt][0], acc[mt][nt][1]);
                __half2 h1 = __floats2half2_rn(acc[mt][nt][2], acc[mt][nt][3]);
                *(__half2*)&Ch[(size_t)r * CONVD + cc]       = h0;
                *(__half2*)&Ch[(size_t)(r + 8) * CONVD + cc] = h1;
            }
        }
    }
}

// ============================================================================
// Fused conv+SiLU+SSD, all-tensor-core (proven R16 version).
// ============================================================================
#define HST  72
#define RSTG (66 * HST * 2)
#define XSH_OFF   0
#define BSH_OFF   8192
#define CSH_OFF   16384
#define GSH_OFF   24576
#define STAGE_OFF 32768
#define SSD_SMEM  (STAGE_OFF + 3 * RSTG)   // 61280

__global__ __launch_bounds__(256, 2) void ssd_chunk_kernel(
    const __half* __restrict__ xbch, const float* __restrict__ cw,
    const float* __restrict__ cb,    __half* __restrict__ chx,
    __half* __restrict__ ydiag,      float* __restrict__ cs)
{
    extern __shared__ __align__(16) char smc[];
    char* XsH = smc + XSH_OFF;
    char* BsH = smc + BSH_OFF;
    char* CsH = smc + CSH_OFF;
    char* GsH = smc + GSH_OFF;
    char* Hs  = smc + STAGE_OFF;

    int bid = blockIdx.x;
    int c  = bid & 63;
    int bh = bid >> 6;
    int h  = bh & 31;
    int b  = bh >> 5;
    int sl0 = c * CHUNK;
    size_t rbase = (size_t)b * SEQ + sl0;
    int tid = threadIdx.x;
    const int wid = tid >> 5, lane = tid & 31;

    for (int i = tid; i < 3 * 66 * 8; i += 256) {
        int reg = i / 528;
        int rem = i - reg * 528;
        int row = rem >> 3;
        int ch  = rem & 7;
        int sl  = sl0 - 1 + row;
        char* dst = Hs + reg * RSTG + row * (HST * 2) + ch * 16;
        if (sl >= 0 && sl < SEQ) {
            cp16(dst, xbch + ((size_t)b * SEQ + sl) * CONVD + reg * 2048 + h * 64 + ch * 8);
        } else {
            sts_zero16(dst);
        }
    }
    asm volatile("cp.async.commit_group;");
    asm volatile("cp.async.wait_group 0;");
    __syncthreads();

#pragma unroll
    for (int reg = 0; reg < 3; reg++) {
        const char* Hreg = Hs + reg * RSTG;
        char* dstH = (reg == 0) ? XsH : (reg == 1) ? BsH : CsH;
        int chbase = reg * 2048 + h * 64;
        for (int i = tid; i < 64 * 16; i += 256) {
            int l = i >> 4, q = (i & 15) * 4;
            size_t r = rbase + l;
            const char* rp = Hreg + l * (HST * 2) + q * 2;
            uint2 um = *(const uint2*)(rp);
            uint2 u0 = *(const uint2*)(rp + HST * 2);
            uint2 up = *(const uint2*)(rp + HST * 4);
            __half2 h0a = *(__half2*)&u0.x, h0b = *(__half2*)&u0.y;
            __half2 hma = *(__half2*)&um.x, hmb = *(__half2*)&um.y;
            __half2 hpa = *(__half2*)&up.x, hpb = *(__half2*)&up.y;
            float4 x0 = make_float4(__low2float(h0a), __high2float(h0a),
                                    __low2float(h0b), __high2float(h0b));
            float4 xm = make_float4(__low2float(hma), __high2float(hma),
                                    __low2float(hmb), __high2float(hmb));
            float4 xp = make_float4(__low2float(hpa), __high2float(hpa),
                                    __low2float(hpb), __high2float(hpb));
            int ch = chbase + q;
            float4 v;
            v.x = fmaf(cw[3*ch+0], xm.x, fmaf(cw[3*ch+1], x0.x, fmaf(cw[3*ch+2], xp.x, cb[ch])));
            v.y = fmaf(cw[3*ch+3], xm.y, fmaf(cw[3*ch+4], x0.y, fmaf(cw[3*ch+5], xp.y, cb[ch+1])));
            v.z = fmaf(cw[3*ch+6], xm.z, fmaf(cw[3*ch+7], x0.z, fmaf(cw[3*ch+8], xp.z, cb[ch+2])));
            v.w = fmaf(cw[3*ch+9], xm.w, fmaf(cw[3*ch+10], x0.w, fmaf(cw[3*ch+11], xp.w, cb[ch+3])));
            v.x = silu(v.x); v.y = silu(v.y); v.z = silu(v.z); v.w = silu(v.w);

            __half2 lo = __floats2half2_rn(v.x, v.y);
            __half2 hi = __floats2half2_rn(v.z, v.w);
            uint2 hv;
            hv.x = *(unsigned*)&lo;
            hv.y = *(unsigned*)&hi;
            int addr = l * 128 + (((q >> 3) ^ (l & 7)) << 4) + ((q & 4) << 1);
            *(uint2*)(dstH + addr) = hv;
            if (reg == 2)
                *(uint2*)&chx[r * DMODEL + h * 64 + q] = hv;
        }
    }
    __syncthreads();

    const unsigned xBase = (unsigned)__cvta_generic_to_shared(XsH);
    const unsigned bBase = (unsigned)__cvta_generic_to_shared(BsH);
    const unsigned cBase = (unsigned)__cvta_generic_to_shared(CsH);
    const unsigned gBase = (unsigned)__cvta_generic_to_shared(GsH);

    const int wrow = (wid & 3) * 16;
    const int wcol = (wid >> 2) * 32;
    const int g  = lane >> 2, t4 = lane & 3;

    // ---- G = C . B^T via MMA; causal mask; store fp16 swizzled GsH ----
    {
        const int ar = wrow + (lane & 15);
        const int acsl = lane >> 4;
        const int br0 = wcol + (lane & 7);
        const int bcsl = (lane >> 3) & 1;

        float acc[4][4];
#pragma unroll
        for (int i = 0; i < 4; i++)
#pragma unroll
            for (int j = 0; j < 4; j++) acc[i][j] = 0.f;

#pragma unroll
        for (int ks = 0; ks < 4; ks++) {
            unsigned a[4];
            unsigned ad = cBase + (unsigned)(ar * 128 + (((2 * ks + acsl) ^ (ar & 7)) << 4));
            asm volatile(
                "ldmatrix.sync.aligned.m8n8.x4.shared.b16 {%0,%1,%2,%3}, [%4];"
                : "=r"(a[0]), "=r"(a[1]), "=r"(a[2]), "=r"(a[3]) : "r"(ad));
#pragma unroll
            for (int nt = 0; nt < 4; nt++) {
                int rr = br0 + nt * 8;
                unsigned bd = bBase + (unsigned)(rr * 128 + (((2 * ks + bcsl) ^ (rr & 7)) << 4));
                unsigned bf0, bf1;
                asm volatile(
                    "ldmatrix.sync.aligned.m8n8.x2.shared.b16 {%0,%1}, [%2];"
                    : "=r"(bf0), "=r"(bf1) : "r"(bd));
                asm volatile(
                    "mma.sync.aligned.m16n8k16.row.col.f32.f16.f16.f32 "
                    "{%0,%1,%2,%3}, {%4,%5,%6,%7}, {%8,%9}, {%0,%1,%2,%3};"
                    : "+f"(acc[nt][0]), "+f"(acc[nt][1]), "+f"(acc[nt][2]), "+f"(acc[nt][3])
                    : "r"(a[0]), "r"(a[1]), "r"(a[2]), "r"(a[3]), "r"(bf0), "r"(bf1));
            }
        }
        int r0 = wrow + g, r1 = r0 + 8;
#pragma unroll
        for (int nt = 0; nt < 4; nt++) {
            int c0 = wcol + nt * 8 + 2 * t4;
            float v00 = (r0 >= c0)     ? acc[nt][0] : 0.f;
            float v01 = (r0 >= c0 + 1) ? acc[nt][1] : 0.f;
            float v10 = (r1 >= c0)     ? acc[nt][2] : 0.f;
            float v11 = (r1 >= c0 + 1) ? acc[nt][3] : 0.f;
            __half2 h0 = __floats2half2_rn(v00, v01);
            __half2 h1 = __floats2half2_rn(v10, v11);
            int a0 = r0 * 128 + (((c0 >> 3) ^ (r0 & 7)) << 4) + 4 * t4;
            int a1 = r1 * 128 + (((c0 >> 3) ^ (r1 & 7)) << 4) + 4 * t4;
            *(__half2*)(GsH + a0) = h0;
            *(__half2*)(GsH + a1) = h1;
        }
    }
    __syncthreads();

    // ---- Y = G . X via MMA (X via ldmatrix.trans) ----
    {
        const int ar = wrow + (lane & 15);
        const int acsl = lane >> 4;

        float acc[4][4];
#pragma unroll
        for (int i = 0; i < 4; i++)
#pragma unroll
            for (int j = 0; j < 4; j++) acc[i][j] = 0.f;

#pragma unroll
        for (int ks = 0; ks < 4; ks++) {
            unsigned a[4];
            unsigned ad = gBase + (unsigned)(ar * 128 + (((2 * ks + acsl) ^ (ar & 7)) << 4));
            asm volatile(
                "ldmatrix.sync.aligned.m8n8.x4.shared.b16 {%0,%1,%2,%3}, [%4];"
                : "=r"(a[0]), "=r"(a[1]), "=r"(a[2]), "=r"(a[3]) : "r"(ad));
            int brr = ks * 16 + (lane & 15);
#pragma unroll
            for (int nt = 0; nt < 4; nt++) {
                int n0 = wcol + nt * 8;
                unsigned bd = xBase + (unsigned)(brr * 128 + (((n0 >> 3) ^ (brr & 7)) << 4));
                unsigned bf0, bf1;
                asm volatile(
                    "ldmatrix.sync.aligned.m8n8.x2.trans.shared.b16 {%0,%1}, [%2];"
                    : "=r"(bf0), "=r"(bf1) : "r"(bd));
                asm volatile(
                    "mma.sync.aligned.m16n8k16.row.col.f32.f16.f16.f32 "
                    "{%0,%1,%2,%3}, {%4,%5,%6,%7}, {%8,%9}, {%0,%1,%2,%3};"
                    : "+f"(acc[nt][0]), "+f"(acc[nt][1]), "+f"(acc[nt][2]), "+f"(acc[nt][3])
                    : "r"(a[0]), "r"(a[1]), "r"(a[2]), "r"(a[3]), "r"(bf0), "r"(bf1));
            }
        }
        int r0 = wrow + g, r1 = r0 + 8;
        __half* y0 = &ydiag[(rbase + r0) * DMODEL + h * 64];
        __half* y1 = &ydiag[(rbase + r1) * DMODEL + h * 64];
#pragma unroll
        for (int nt = 0; nt < 4; nt++) {
            int c0 = wcol + nt * 8 + 2 * t4;
            *(__half2*)&y0[c0] = __floats2half2_rn(acc[nt][0], acc[nt][1]);
            *(__half2*)&y1[c0] = __floats2half2_rn(acc[nt][2], acc[nt][3]);
        }
    }

    // ---- chunk state from fp16 tiles (fp32 accumulate) ----
    if (tid < 64) {
        int n = tid;
        int chn = n >> 3, off = (n & 7) * 2;
        float a = 0.f;
#pragma unroll 8
        for (int l = 0; l < 64; l++) {
            int sw = l * 128 + ((chn ^ (l & 7)) << 4) + off;
            float xv = __half2float(*(const __half*)(XsH + sw));
            float bv = __half2float(*(const __half*)(BsH + sw));
            a = fmaf(xv, bv, a);
        }
        cs[(size_t)bid * 64 + n] = a;
    }
}

// ============================================================================
// Inter-chunk scan
// ============================================================================
__global__ void scan_kernel(const float* __restrict__ cs, const float* __restrict__ A_log,
                            float* __restrict__ prev)
{
    int bh = blockIdx.x;
    int h  = bh & 31;
    int n  = threadIdx.x;
    float d = __expf(63.f * A_log[h]);
    float s = 0.f;
    for (int c = 0; c < NCHUNK; c++) {
        size_t idx = ((size_t)bh * NCHUNK + c) * 64 + n;
        prev[idx] = s;
        s = s * d + cs[idx];
    }
}

// ============================================================================
// Y = Y_diag + Y_off; gate silu(z); RMSNorm. Vectorized.
// ============================================================================
__global__ __launch_bounds__(256) void combine_kernel(
    const __half* __restrict__ ydiag, const float* __restrict__ gz,
    const __half* __restrict__ chx,   const float* __restrict__ prev,
    const float* __restrict__ rms_w,  __half* __restrict__ yn)
{
    int r = blockIdx.x;
    int b = r >> 12;
    int l = r & (SEQ - 1);
    int c = l >> 6;

    __shared__ float sh_yoff[NHEADS];
    __shared__ float sh_red[8];

    int tid = threadIdx.x, warp = tid >> 5, lane = tid & 31;

    for (int h = warp; h < NHEADS; h += 8) {
        const __half* Crow = chx + (size_t)r * DMODEL + h * 64;
        const float* pv    = prev + ((size_t)(b * NHEADS + h) * NCHUNK + c) * 64;
        int n0 = lane * 2;
        float v = __half2float(Crow[n0]) * pv[n0] + __half2float(Crow[n0 + 1]) * pv[n0 + 1];
#pragma unroll
        for (int o = 16; o; o >>= 1) v += __shfl_down_sync(0xffffffffu, v, o);
        if (lane == 0) sh_yoff[h] = v;
    }
    __syncthreads();

    const int d0 = tid * 8;
    float4 z0 = *(const float4*)&gz[(size_t)r * DMODEL + d0];
    float4 z1 = *(const float4*)&gz[(size_t)r * DMODEL + d0 + 4];
    uint4 yd  = *(const uint4*)&ydiag[(size_t)r * DMODEL + d0];
    __half2 y01 = *(__half2*)&yd.x, y23 = *(__half2*)&yd.y;
    __half2 y45 = *(__half2*)&yd.z, y67 = *(__half2*)&yd.w;
    float yoff = sh_yoff[d0 >> 6];

    float vals[8];
    vals[0] = (__low2float(y01)  + yoff) * silu(z0.x);
    vals[1] = (__high2float(y01) + yoff) * silu(z0.y);
    vals[2] = (__low2float(y23)  + yoff) * silu(z0.z);
    vals[3] = (__high2float(y23) + yoff) * silu(z0.w);
    vals[4] = (__low2float(y45)  + yoff) * silu(z1.x);
    vals[5] = (__high2float(y45) + yoff) * silu(z1.y);
    vals[6] = (__low2float(y67)  + yoff) * silu(z1.z);
    vals[7] = (__high2float(y67) + yoff) * silu(z1.w);

    float ss = 0.f;
#pragma unroll
    for (int j = 0; j < 8; j++) ss += vals[j] * vals[j];
#pragma unroll
    for (int o = 16; o; o >>= 1) ss += __shfl_down_sync(0xffffffffu, ss, o);
    if (lane == 0) sh_red[warp] = ss;
    __syncthreads();
    if (tid == 0) {
        float t = 0.f;
#pragma unroll
        for (int w = 0; w < 8; w++) t += sh_red[w];
        sh_red[0] = rsqrtf(t / (float)DMODEL + RMS_EPS);
    }
    __syncthreads();
    float scale = sh_red[0];

    float4 rw0 = *(const float4*)&rms_w[d0];
    float4 rw1 = *(const float4*)&rms_w[d0 + 4];
    __half2 o0 = __floats2half2_rn(vals[0] * scale * rw0.x, vals[1] * scale * rw0.y);
    __half2 o1 = __floats2half2_rn(vals[2] * scale * rw0.z, vals[3] * scale * rw0.w);
    __half2 o2 = __floats2half2_rn(vals[4] * scale * rw1.x, vals[5] * scale * rw1.y);
    __half2 o3 = __floats2half2_rn(vals[6] * scale * rw1.z, vals[7] * scale * rw1.w);
    uint4 ov = make_uint4(*(unsigned*)&o0, *(unsigned*)&o1, *(unsigned*)&o2, *(unsigned*)&o3);
    *(uint4*)&yn[(size_t)r * DMODEL + d0] = ov;
}

// ============================================================================
// launch
// ============================================================================
extern "C" void kernel_launch(void* const* d_in, const int* in_sizes, int n_in,
                              void* d_out, int out_size)
{
    const float* u      = (const float*)d_in[0];
    const float* W_in   = (const float*)d_in[1];
    const float* W_out  = (const float*)d_in[2];
    const float* conv_w = (const float*)d_in[3];
    const float* conv_b = (const float*)d_in[4];
    const float* A_log  = (const float*)d_in[5];
    const float* rms_w  = (const float*)d_in[6];
    float* out = (float*)d_out;

    float *gz, *cs, *prev;
    __half *xbch, *chx, *y, *yn, *ut, *wit, *wot;
    cudaGetSymbolAddress((void**)&gz,   g_z);
    cudaGetSymbolAddress((void**)&xbch, g_xbch);
    cudaGetSymbolAddress((void**)&chx,  g_ch);
    cudaGetSymbolAddress((void**)&y,    g_y);
    cudaGetSymbolAddress((void**)&yn,   g_yn);
    cudaGetSymbolAddress((void**)&cs,   g_cs);
    cudaGetSymbolAddress((void**)&prev, g_prev);
    cudaGetSymbolAddress((void**)&ut,   g_ut);
    cudaGetSymbolAddress((void**)&wit,  g_wit);
    cudaGetSymbolAddress((void**)&wot,  g_wot);

    static bool attr_done = false;
    if (!attr_done) {
        cudaFuncSetAttribute(gemm_tn_f16<true>,  cudaFuncAttributeMaxDynamicSharedMemorySize, GSMEM);
        cudaFuncSetAttribute(gemm_tn_f16<false>, cudaFuncAttributeMaxDynamicSharedMemorySize, GSMEM);
        cudaFuncSetAttribute(ssd_chunk_kernel, cudaFuncAttributeMaxDynamicSharedMemorySize, SSD_SMEM);
        attr_done = true;
    }

    // 0) convert u, W_in, W_out to fp16 in ONE launch
    {
        size_t n4u = (size_t)ROWS * DMODEL / 4;
        size_t n4w = (size_t)ZXB_LD * DMODEL / 4;
        size_t n4o = (size_t)DMODEL * DMODEL / 4;
        size_t tot = n4u + n4w + n4o;
        h_convert3<<<(unsigned)((tot + 255) / 256), 256>>>(u, ut, n4u, W_in, wit, n4w, W_out, wot, n4o);
    }
    // 1) split GEMM1: z -> fp32 gz, xBC -> fp16 xbch
    gemm_tn_f16<true><<<dim3(ZXB_LD / 128, ROWS / 128), 256, GSMEM>>>(
        ut, wit, gz, xbch, ROWS, ZXB_LD, DMODEL);
    // 2) fused conv + silu + per-chunk SSD (all tensor-core)
    ssd_chunk_kernel<<<BATCH * NHEADS * NCHUNK, 256, SSD_SMEM>>>(xbch, conv_w, conv_b, chx, y, cs);
    // 3) inter-chunk scan
    scan_kernel<<<BATCH * NHEADS, 64>>>(cs, A_log, prev);
    // 4) Y_off + gate + rmsnorm
    combine_kernel<<<ROWS, 256>>>(y, gz, chx, prev, rms_w, yn);
    // 5) out = yn @ W_out^T (fp32 out)
    gemm_tn_f16<false><<<dim3(DMODEL / 128, ROWS / 128), 256, GSMEM>>>(
        yn, wot, out, (__half*)nullptr, ROWS, DMODEL, DMODEL);
}